// round 14
// baseline (speedup 1.0000x reference)
#include <cuda_runtime.h>
#include <cuda_bf16.h>
#include <cstdint>

// Problem constants (fixed by reference setup_inputs)
#define N_NODES 50000
#define D_IN    128
#define D_OUT   128
#define N_EDGES 800000
#define NSEG    (2 * N_NODES)     // segment key = set*50000 + dst

// ---------------------------------------------------------------------------
// Device scratch (static — no allocation allowed)
// ---------------------------------------------------------------------------
// Pre-activations, interleaved per row: [row*256+0..127]=x@W0, [+128..255]=x@W1
__device__ float g_pre[(size_t)N_NODES * 256];
// CSR build state
__device__ int  g_cnt[NSEG];
__device__ int  g_off[NSEG + 1];
__device__ int  g_cursor[NSEG];
// Packed edge entries: .x = src*256 + set*128 (gather base into g_pre),
//                      .y = float bits of edge value
__device__ int2 g_entries[2 * N_EDGES];

// ---------------------------------------------------------------------------
// Kernel: zero the segment counters
// ---------------------------------------------------------------------------
__global__ void zero_cnt_kernel() {
    int i = blockIdx.x * blockDim.x + threadIdx.x;
    if (i < NSEG) g_cnt[i] = 0;
}

// ---------------------------------------------------------------------------
// Kernel: histogram of dst per segment (both edge sets in one grid)
// ---------------------------------------------------------------------------
__global__ __launch_bounds__(256)
void hist_kernel(const int* __restrict__ idx0, const int* __restrict__ idx1) {
    int i = blockIdx.x * blockDim.x + threadIdx.x;
    if (i >= 2 * N_EDGES) return;
    int set = (i >= N_EDGES) ? 1 : 0;
    int e   = i - set * N_EDGES;
    const int* __restrict__ idx = set ? idx1 : idx0;
    int dst = __ldg(idx + e);                     // edge_index[0] = dst
    atomicAdd(&g_cnt[set * N_NODES + dst], 1);
}

// ---------------------------------------------------------------------------
// Kernel: exclusive scan of 100000 counts (single block, 1024 threads)
// Writes g_off[0..NSEG] and initializes g_cursor.
// ---------------------------------------------------------------------------
__global__ __launch_bounds__(1024)
void scan_kernel() {
    __shared__ int sums[1024];
    const int CH = (NSEG + 1023) / 1024;          // 98
    int t = threadIdx.x;
    int base = t * CH;

    int s = 0;
    for (int k = 0; k < CH; k++) {
        int j = base + k;
        if (j < NSEG) s += g_cnt[j];
    }
    sums[t] = s;
    __syncthreads();

    // Hillis-Steele inclusive scan over 1024 thread sums
    for (int d = 1; d < 1024; d <<= 1) {
        int v = (t >= d) ? sums[t - d] : 0;
        __syncthreads();
        sums[t] += v;
        __syncthreads();
    }

    int off = sums[t] - s;                        // exclusive prefix
    for (int k = 0; k < CH; k++) {
        int j = base + k;
        if (j < NSEG) {
            int c = g_cnt[j];
            g_off[j]    = off;
            g_cursor[j] = off;
            off += c;
        }
    }
    if (t == 1023) g_off[NSEG] = off;             // total = 2*N_EDGES
}

// ---------------------------------------------------------------------------
// Kernel: scatter edges into CSR entry array
// ---------------------------------------------------------------------------
__global__ __launch_bounds__(256)
void scatter_kernel(const float* __restrict__ vals0, const float* __restrict__ vals1,
                    const int* __restrict__ idx0,  const int* __restrict__ idx1) {
    int i = blockIdx.x * blockDim.x + threadIdx.x;
    if (i >= 2 * N_EDGES) return;
    int set = (i >= N_EDGES) ? 1 : 0;
    int e   = i - set * N_EDGES;
    const int*   __restrict__ idx = set ? idx1  : idx0;
    const float* __restrict__ vv  = set ? vals1 : vals0;

    int   dst = __ldg(idx + e);
    int   src = __ldg(idx + N_EDGES + e);
    float v   = __ldg(vv + e);

    int pos = atomicAdd(&g_cursor[set * N_NODES + dst], 1);
    g_entries[pos] = make_int2(src * 256 + set * 128, __float_as_int(v));
}

// ---------------------------------------------------------------------------
// Kernel: SGEMM  g_pre[:, set*128 : +128] = X @ (set==0 ? W0 : W1)
// BM=128, BN=128, BK=16, 256 threads, 8x8 micro-tile.
// ---------------------------------------------------------------------------
#define BM 128
#define BN 128
#define BK 16

__global__ __launch_bounds__(256, 2)
void gemm_kernel(const float* __restrict__ X,
                 const float* __restrict__ W0,
                 const float* __restrict__ W1) {
    __shared__ float As[BK][BM];
    __shared__ float Bs[BK][BN];

    const int mTile = blockIdx.x * BM;
    const float* __restrict__ W = (blockIdx.y == 0) ? W0 : W1;
    const int nOff = blockIdx.y * 128;

    const int tid = threadIdx.x;
    const int tx = tid & 15;
    const int ty = tid >> 4;

    float acc[8][8];
#pragma unroll
    for (int i = 0; i < 8; i++)
#pragma unroll
        for (int j = 0; j < 8; j++) acc[i][j] = 0.f;

    const int aRow0 = tid >> 2;
    const int aCol4 = (tid & 3) * 4;
    const int bRow0 = tid >> 5;
    const int bCol4 = (tid & 31) * 4;

    for (int k0 = 0; k0 < D_IN; k0 += BK) {
#pragma unroll
        for (int h = 0; h < 2; h++) {
            int row = aRow0 + h * 64;
            int grow = mTile + row;
            float4 v = make_float4(0.f, 0.f, 0.f, 0.f);
            if (grow < N_NODES)
                v = *reinterpret_cast<const float4*>(X + (size_t)grow * D_IN + k0 + aCol4);
            As[aCol4 + 0][row] = v.x;
            As[aCol4 + 1][row] = v.y;
            As[aCol4 + 2][row] = v.z;
            As[aCol4 + 3][row] = v.w;
        }
#pragma unroll
        for (int h = 0; h < 2; h++) {
            int krow = bRow0 + h * 8;
            float4 v = *reinterpret_cast<const float4*>(W + (size_t)(k0 + krow) * 128 + bCol4);
            *reinterpret_cast<float4*>(&Bs[krow][bCol4]) = v;
        }
        __syncthreads();

#pragma unroll
        for (int k = 0; k < BK; k++) {
            float4 a0 = *reinterpret_cast<const float4*>(&As[k][ty * 8]);
            float4 a1 = *reinterpret_cast<const float4*>(&As[k][ty * 8 + 4]);
            float4 b0 = *reinterpret_cast<const float4*>(&Bs[k][tx * 8]);
            float4 b1 = *reinterpret_cast<const float4*>(&Bs[k][tx * 8 + 4]);
            float a[8] = {a0.x, a0.y, a0.z, a0.w, a1.x, a1.y, a1.z, a1.w};
            float b[8] = {b0.x, b0.y, b0.z, b0.w, b1.x, b1.y, b1.z, b1.w};
#pragma unroll
            for (int i = 0; i < 8; i++)
#pragma unroll
                for (int j = 0; j < 8; j++)
                    acc[i][j] = fmaf(a[i], b[j], acc[i][j]);
        }
        __syncthreads();
    }

#pragma unroll
    for (int i = 0; i < 8; i++) {
        int grow = mTile + ty * 8 + i;
        if (grow >= N_NODES) break;
        float* dst = g_pre + (size_t)grow * 256 + nOff + tx * 8;
        *reinterpret_cast<float4*>(dst)     = make_float4(acc[i][0], acc[i][1], acc[i][2], acc[i][3]);
        *reinterpret_cast<float4*>(dst + 4) = make_float4(acc[i][4], acc[i][5], acc[i][6], acc[i][7]);
    }
}

// ---------------------------------------------------------------------------
// Kernel: CSR SpMM — one warp per dst row, register accumulation,
// fused bias + ReLU, single store. Entries broadcast via shuffles.
// ---------------------------------------------------------------------------
__global__ __launch_bounds__(256)
void spmm_csr_kernel(const float* __restrict__ bias, float* __restrict__ out) {
    const int warp = (blockIdx.x * blockDim.x + threadIdx.x) >> 5;
    const int lane = threadIdx.x & 31;
    if (warp >= N_NODES) return;
    const int r = warp;

    float4 acc = make_float4(0.f, 0.f, 0.f, 0.f);

#pragma unroll
    for (int set = 0; set < 2; set++) {
        int seg = set * N_NODES + r;
        int s   = __ldg(&g_off[seg]);
        int end = __ldg(&g_off[seg + 1]);

        for (int e = s; e < end; e += 32) {
            int n = min(32, end - e);
            int2 ent = (lane < n) ? g_entries[e + lane] : make_int2(0, 0);
            for (int j = 0; j < n; j++) {
                int   col = __shfl_sync(0xFFFFFFFFu, ent.x, j);
                float v   = __int_as_float(__shfl_sync(0xFFFFFFFFu, ent.y, j));
                float4 p  = *reinterpret_cast<const float4*>(g_pre + col + lane * 4);
                acc.x = fmaf(v, p.x, acc.x);
                acc.y = fmaf(v, p.y, acc.y);
                acc.z = fmaf(v, p.z, acc.z);
                acc.w = fmaf(v, p.w, acc.w);
            }
        }
    }

    float4 b = *reinterpret_cast<const float4*>(bias + lane * 4);
    acc.x = fmaxf(acc.x + b.x, 0.f);
    acc.y = fmaxf(acc.y + b.y, 0.f);
    acc.z = fmaxf(acc.z + b.z, 0.f);
    acc.w = fmaxf(acc.w + b.w, 0.f);
    *reinterpret_cast<float4*>(out + (size_t)r * D_OUT + lane * 4) = acc;
}

// ---------------------------------------------------------------------------
// Launch. Inputs: x, W0, W1, bias, edge_vals0, edge_vals1, edge_index0, edge_index1
// ---------------------------------------------------------------------------
extern "C" void kernel_launch(void* const* d_in, const int* in_sizes, int n_in,
                              void* d_out, int out_size) {
    const float* x    = (const float*)d_in[0];
    const float* W0   = (const float*)d_in[1];
    const float* W1   = (const float*)d_in[2];
    const float* bias = (const float*)d_in[3];
    const float* ev0  = (const float*)d_in[4];
    const float* ev1  = (const float*)d_in[5];
    const int*   ei0  = (const int*)d_in[6];
    const int*   ei1  = (const int*)d_in[7];
    float*       out  = (float*)d_out;

    const int edgeThreads = 2 * N_EDGES;

    // CSR build
    zero_cnt_kernel<<<(NSEG + 255) / 256, 256>>>();
    hist_kernel<<<(edgeThreads + 255) / 256, 256>>>(ei0, ei1);
    scan_kernel<<<1, 1024>>>();
    scatter_kernel<<<(edgeThreads + 255) / 256, 256>>>(ev0, ev1, ei0, ei1);

    // Dense GEMM: g_pre = x @ [W0 | W1]
    dim3 gGrid((N_NODES + BM - 1) / BM, 2);
    gemm_kernel<<<gGrid, 256>>>(x, W0, W1);

    // CSR SpMM with fused bias + ReLU
    const int spmmWarps = N_NODES;
    spmm_csr_kernel<<<(spmmWarps * 32 + 255) / 256, 256>>>(bias, out);
}

// round 15
// speedup vs baseline: 1.7517x; 1.7517x over previous
#include <cuda_runtime.h>
#include <cuda_bf16.h>
#include <cstdint>

// Problem constants (fixed by reference setup_inputs)
#define N_NODES 50000
#define D_IN    128
#define D_OUT   128
#define N_EDGES 800000
#define NSEG    (2 * N_NODES)          // segment key = set*50000 + dst
#define SCAN_BLK_ITEMS 1024
#define SCAN_NBLK ((NSEG + SCAN_BLK_ITEMS - 1) / SCAN_BLK_ITEMS)   // 98

// ---------------------------------------------------------------------------
// Device scratch (static — no allocation allowed)
// ---------------------------------------------------------------------------
// Pre-activations, interleaved per row: [row*256+0..127]=x@W0, [+128..255]=x@W1
__device__ float g_pre[(size_t)N_NODES * 256];
// CSR build state. g_cnt doubles as the scatter cursor after the scan.
__device__ int  g_cnt[NSEG];
__device__ int  g_off[NSEG + 1];
__device__ int  g_blocksums[SCAN_NBLK];
__device__ int  g_blockoff[SCAN_NBLK];
// Packed edge entries: .x = src*256 + set*128 (gather base into g_pre),
//                      .y = float bits of edge value
__device__ int2 g_entries[2 * N_EDGES];

// ---------------------------------------------------------------------------
// Kernel: zero the segment counters
// ---------------------------------------------------------------------------
__global__ void zero_cnt_kernel() {
    int i = blockIdx.x * blockDim.x + threadIdx.x;
    if (i < NSEG) g_cnt[i] = 0;
}

// ---------------------------------------------------------------------------
// Kernel: histogram of dst per segment (both edge sets in one grid)
// ---------------------------------------------------------------------------
__global__ __launch_bounds__(256)
void hist_kernel(const int* __restrict__ idx0, const int* __restrict__ idx1) {
    int i = blockIdx.x * blockDim.x + threadIdx.x;
    if (i >= 2 * N_EDGES) return;
    int set = (i >= N_EDGES) ? 1 : 0;
    int e   = i - set * N_EDGES;
    const int* __restrict__ idx = set ? idx1 : idx0;
    int dst = __ldg(idx + e);                     // edge_index[0] = dst
    atomicAdd(&g_cnt[set * N_NODES + dst], 1);
}

// ---------------------------------------------------------------------------
// Two-level exclusive scan of g_cnt -> g_off (+ cursor re-init into g_cnt)
// ---------------------------------------------------------------------------
// Pass 1: per-block (1024 items, 256 threads x 4) sums
__global__ __launch_bounds__(256)
void scan_blocksum_kernel() {
    __shared__ int warpsums[8];
    int b = blockIdx.x, t = threadIdx.x;
    int base = b * SCAN_BLK_ITEMS + t * 4;
    int s = 0;
#pragma unroll
    for (int k = 0; k < 4; k++) {
        int j = base + k;
        if (j < NSEG) s += g_cnt[j];
    }
    // warp reduce
    for (int o = 16; o > 0; o >>= 1) s += __shfl_down_sync(0xFFFFFFFFu, s, o);
    if ((t & 31) == 0) warpsums[t >> 5] = s;
    __syncthreads();
    if (t == 0) {
        int tot = 0;
#pragma unroll
        for (int w = 0; w < 8; w++) tot += warpsums[w];
        g_blocksums[b] = tot;
    }
}

// Pass 2: scan 98 block sums (single block, 128 threads)
__global__ __launch_bounds__(128)
void scan_top_kernel() {
    __shared__ int sh[128];
    int t = threadIdx.x;
    int v = (t < SCAN_NBLK) ? g_blocksums[t] : 0;
    sh[t] = v;
    __syncthreads();
    for (int d = 1; d < 128; d <<= 1) {
        int y = (t >= d) ? sh[t - d] : 0;
        __syncthreads();
        sh[t] += y;
        __syncthreads();
    }
    if (t < SCAN_NBLK) g_blockoff[t] = sh[t] - v;      // exclusive
    if (t == 127) g_off[NSEG] = sh[127];                // total = 2*N_EDGES
}

// Pass 3: per-block exclusive scan + block base; writes g_off and
// re-initializes g_cnt as the scatter cursor.
__global__ __launch_bounds__(256)
void scan_final_kernel() {
    __shared__ int warpsums[8];
    int b = blockIdx.x, t = threadIdx.x;
    int lane = t & 31, w = t >> 5;
    int base = b * SCAN_BLK_ITEMS + t * 4;

    int c0 = 0, c1 = 0, c2 = 0, c3 = 0;
    if (base + 0 < NSEG) c0 = g_cnt[base + 0];
    if (base + 1 < NSEG) c1 = g_cnt[base + 1];
    if (base + 2 < NSEG) c2 = g_cnt[base + 2];
    if (base + 3 < NSEG) c3 = g_cnt[base + 3];
    int tsum = c0 + c1 + c2 + c3;

    // warp inclusive scan of thread sums
    int inc = tsum;
    for (int o = 1; o < 32; o <<= 1) {
        int y = __shfl_up_sync(0xFFFFFFFFu, inc, o);
        if (lane >= o) inc += y;
    }
    if (lane == 31) warpsums[w] = inc;
    __syncthreads();
    if (w == 0) {
        int ws = (lane < 8) ? warpsums[lane] : 0;
        for (int o = 1; o < 8; o <<= 1) {
            int y = __shfl_up_sync(0xFFFFFFFFu, ws, o);
            if (lane >= o) ws += y;
        }
        if (lane < 8) warpsums[lane] = ws;
    }
    __syncthreads();

    int texcl = g_blockoff[b] + (w ? warpsums[w - 1] : 0) + (inc - tsum);
    int o0 = texcl;
    int o1 = o0 + c0;
    int o2 = o1 + c1;
    int o3 = o2 + c2;
    if (base + 0 < NSEG) { g_off[base + 0] = o0; g_cnt[base + 0] = o0; }
    if (base + 1 < NSEG) { g_off[base + 1] = o1; g_cnt[base + 1] = o1; }
    if (base + 2 < NSEG) { g_off[base + 2] = o2; g_cnt[base + 2] = o2; }
    if (base + 3 < NSEG) { g_off[base + 3] = o3; g_cnt[base + 3] = o3; }
}

// ---------------------------------------------------------------------------
// Kernel: scatter edges into CSR entry array (g_cnt = cursor)
// ---------------------------------------------------------------------------
__global__ __launch_bounds__(256)
void scatter_kernel(const float* __restrict__ vals0, const float* __restrict__ vals1,
                    const int* __restrict__ idx0,  const int* __restrict__ idx1) {
    int i = blockIdx.x * blockDim.x + threadIdx.x;
    if (i >= 2 * N_EDGES) return;
    int set = (i >= N_EDGES) ? 1 : 0;
    int e   = i - set * N_EDGES;
    const int*   __restrict__ idx = set ? idx1  : idx0;
    const float* __restrict__ vv  = set ? vals1 : vals0;

    int   dst = __ldg(idx + e);
    int   src = __ldg(idx + N_EDGES + e);
    float v   = __ldg(vv + e);

    int pos = atomicAdd(&g_cnt[set * N_NODES + dst], 1);
    g_entries[pos] = make_int2(src * 256 + set * 128, __float_as_int(v));
}

// ---------------------------------------------------------------------------
// Kernel: SGEMM  g_pre[:, set*128 : +128] = X @ (set==0 ? W0 : W1)
// BM=128, BN=128, BK=16, 256 threads, 8x8 micro-tile.
// ---------------------------------------------------------------------------
#define BM 128
#define BN 128
#define BK 16

__global__ __launch_bounds__(256, 2)
void gemm_kernel(const float* __restrict__ X,
                 const float* __restrict__ W0,
                 const float* __restrict__ W1) {
    __shared__ float As[BK][BM];
    __shared__ float Bs[BK][BN];

    const int mTile = blockIdx.x * BM;
    const float* __restrict__ W = (blockIdx.y == 0) ? W0 : W1;
    const int nOff = blockIdx.y * 128;

    const int tid = threadIdx.x;
    const int tx = tid & 15;
    const int ty = tid >> 4;

    float acc[8][8];
#pragma unroll
    for (int i = 0; i < 8; i++)
#pragma unroll
        for (int j = 0; j < 8; j++) acc[i][j] = 0.f;

    const int aRow0 = tid >> 2;
    const int aCol4 = (tid & 3) * 4;
    const int bRow0 = tid >> 5;
    const int bCol4 = (tid & 31) * 4;

    for (int k0 = 0; k0 < D_IN; k0 += BK) {
#pragma unroll
        for (int h = 0; h < 2; h++) {
            int row = aRow0 + h * 64;
            int grow = mTile + row;
            float4 v = make_float4(0.f, 0.f, 0.f, 0.f);
            if (grow < N_NODES)
                v = *reinterpret_cast<const float4*>(X + (size_t)grow * D_IN + k0 + aCol4);
            As[aCol4 + 0][row] = v.x;
            As[aCol4 + 1][row] = v.y;
            As[aCol4 + 2][row] = v.z;
            As[aCol4 + 3][row] = v.w;
        }
#pragma unroll
        for (int h = 0; h < 2; h++) {
            int krow = bRow0 + h * 8;
            float4 v = *reinterpret_cast<const float4*>(W + (size_t)(k0 + krow) * 128 + bCol4);
            *reinterpret_cast<float4*>(&Bs[krow][bCol4]) = v;
        }
        __syncthreads();

#pragma unroll
        for (int k = 0; k < BK; k++) {
            float4 a0 = *reinterpret_cast<const float4*>(&As[k][ty * 8]);
            float4 a1 = *reinterpret_cast<const float4*>(&As[k][ty * 8 + 4]);
            float4 b0 = *reinterpret_cast<const float4*>(&Bs[k][tx * 8]);
            float4 b1 = *reinterpret_cast<const float4*>(&Bs[k][tx * 8 + 4]);
            float a[8] = {a0.x, a0.y, a0.z, a0.w, a1.x, a1.y, a1.z, a1.w};
            float b[8] = {b0.x, b0.y, b0.z, b0.w, b1.x, b1.y, b1.z, b1.w};
#pragma unroll
            for (int i = 0; i < 8; i++)
#pragma unroll
                for (int j = 0; j < 8; j++)
                    acc[i][j] = fmaf(a[i], b[j], acc[i][j]);
        }
        __syncthreads();
    }

#pragma unroll
    for (int i = 0; i < 8; i++) {
        int grow = mTile + ty * 8 + i;
        if (grow >= N_NODES) break;
        float* dst = g_pre + (size_t)grow * 256 + nOff + tx * 8;
        *reinterpret_cast<float4*>(dst)     = make_float4(acc[i][0], acc[i][1], acc[i][2], acc[i][3]);
        *reinterpret_cast<float4*>(dst + 4) = make_float4(acc[i][4], acc[i][5], acc[i][6], acc[i][7]);
    }
}

// ---------------------------------------------------------------------------
// Kernel: CSR SpMM — one warp per dst row, register accumulation,
// fused bias + ReLU, single store. Entries read warp-uniform (L1 broadcast),
// inner loop unrolled x2 for gather MLP.
// ---------------------------------------------------------------------------
__global__ __launch_bounds__(256)
void spmm_csr_kernel(const float* __restrict__ bias, float* __restrict__ out) {
    const int warp = (blockIdx.x * blockDim.x + threadIdx.x) >> 5;
    const int lane = threadIdx.x & 31;
    if (warp >= N_NODES) return;
    const int r = warp;
    const int lo = lane * 4;

    float4 acc = make_float4(0.f, 0.f, 0.f, 0.f);

#pragma unroll
    for (int set = 0; set < 2; set++) {
        int seg = set * N_NODES + r;
        int e   = __ldg(&g_off[seg]);
        int end = __ldg(&g_off[seg + 1]);

        for (; e + 1 < end; e += 2) {
            int2 e0 = __ldg(&g_entries[e]);
            int2 e1 = __ldg(&g_entries[e + 1]);
            float4 p0 = *reinterpret_cast<const float4*>(g_pre + e0.x + lo);
            float4 p1 = *reinterpret_cast<const float4*>(g_pre + e1.x + lo);
            float v0 = __int_as_float(e0.y);
            float v1 = __int_as_float(e1.y);
            acc.x = fmaf(v0, p0.x, acc.x);
            acc.y = fmaf(v0, p0.y, acc.y);
            acc.z = fmaf(v0, p0.z, acc.z);
            acc.w = fmaf(v0, p0.w, acc.w);
            acc.x = fmaf(v1, p1.x, acc.x);
            acc.y = fmaf(v1, p1.y, acc.y);
            acc.z = fmaf(v1, p1.z, acc.z);
            acc.w = fmaf(v1, p1.w, acc.w);
        }
        if (e < end) {
            int2 e0 = __ldg(&g_entries[e]);
            float4 p0 = *reinterpret_cast<const float4*>(g_pre + e0.x + lo);
            float v0 = __int_as_float(e0.y);
            acc.x = fmaf(v0, p0.x, acc.x);
            acc.y = fmaf(v0, p0.y, acc.y);
            acc.z = fmaf(v0, p0.z, acc.z);
            acc.w = fmaf(v0, p0.w, acc.w);
        }
    }

    float4 b = *reinterpret_cast<const float4*>(bias + lo);
    acc.x = fmaxf(acc.x + b.x, 0.f);
    acc.y = fmaxf(acc.y + b.y, 0.f);
    acc.z = fmaxf(acc.z + b.z, 0.f);
    acc.w = fmaxf(acc.w + b.w, 0.f);
    *reinterpret_cast<float4*>(out + (size_t)r * D_OUT + lo) = acc;
}

// ---------------------------------------------------------------------------
// Launch. Inputs: x, W0, W1, bias, edge_vals0, edge_vals1, edge_index0, edge_index1
// ---------------------------------------------------------------------------
extern "C" void kernel_launch(void* const* d_in, const int* in_sizes, int n_in,
                              void* d_out, int out_size) {
    const float* x    = (const float*)d_in[0];
    const float* W0   = (const float*)d_in[1];
    const float* W1   = (const float*)d_in[2];
    const float* bias = (const float*)d_in[3];
    const float* ev0  = (const float*)d_in[4];
    const float* ev1  = (const float*)d_in[5];
    const int*   ei0  = (const int*)d_in[6];
    const int*   ei1  = (const int*)d_in[7];
    float*       out  = (float*)d_out;

    const int edgeThreads = 2 * N_EDGES;

    // CSR build
    zero_cnt_kernel<<<(NSEG + 255) / 256, 256>>>();
    hist_kernel<<<(edgeThreads + 255) / 256, 256>>>(ei0, ei1);
    scan_blocksum_kernel<<<SCAN_NBLK, 256>>>();
    scan_top_kernel<<<1, 128>>>();
    scan_final_kernel<<<SCAN_NBLK, 256>>>();
    scatter_kernel<<<(edgeThreads + 255) / 256, 256>>>(ev0, ev1, ei0, ei1);

    // Dense GEMM: g_pre = x @ [W0 | W1]
    dim3 gGrid((N_NODES + BM - 1) / BM, 2);
    gemm_kernel<<<gGrid, 256>>>(x, W0, W1);

    // CSR SpMM with fused bias + ReLU
    spmm_csr_kernel<<<(N_NODES * 32 + 255) / 256, 256>>>(bias, out);
}

// round 16
// speedup vs baseline: 2.3965x; 1.3681x over previous
#include <cuda_runtime.h>
#include <cuda_bf16.h>
#include <cstdint>

// Problem constants (fixed by reference setup_inputs)
#define N_NODES 50000
#define D_IN    128
#define D_OUT   128
#define N_EDGES 800000
#define NSEG    (2 * N_NODES)          // segment key = set*50000 + dst
#define SCAN_BLK_ITEMS 1024
#define SCAN_NBLK ((NSEG + SCAN_BLK_ITEMS - 1) / SCAN_BLK_ITEMS)   // 98

// ---------------------------------------------------------------------------
// Device scratch (static — no allocation allowed)
// ---------------------------------------------------------------------------
// Pre-activations, interleaved per row: [row*256+0..127]=x@W0, [+128..255]=x@W1
__device__ float g_pre[(size_t)N_NODES * 256];
// CSR build state. g_cnt doubles as the scatter cursor after the scan.
__device__ int  g_cnt[NSEG];
__device__ int  g_off[NSEG + 1];
__device__ int  g_blocksums[SCAN_NBLK];
__device__ int  g_blockoff[SCAN_NBLK];
// Packed edge entries: .x = src*256 + set*128, .y = float bits of edge value
__device__ int2 g_entries[2 * N_EDGES];
// Split-precision weights, transposed: Bt[n][k] = W_set[k][n&127], n in [0,256)
__device__ __nv_bfloat16 g_Bt_hi[256 * 128];
__device__ __nv_bfloat16 g_Bt_lo[256 * 128];

// ---------------------------------------------------------------------------
// PTX helpers (mma.sync bf16 path)
// ---------------------------------------------------------------------------
__device__ __forceinline__ uint32_t smem_u32(const void* p) {
    return (uint32_t)__cvta_generic_to_shared(p);
}
__device__ __forceinline__ void ldm_x4(uint32_t* r, uint32_t a) {
    asm volatile("ldmatrix.sync.aligned.m8n8.x4.shared.b16 {%0,%1,%2,%3}, [%4];"
                 : "=r"(r[0]), "=r"(r[1]), "=r"(r[2]), "=r"(r[3]) : "r"(a));
}
__device__ __forceinline__ void ldm_x2(uint32_t* r, uint32_t a) {
    asm volatile("ldmatrix.sync.aligned.m8n8.x2.shared.b16 {%0,%1}, [%2];"
                 : "=r"(r[0]), "=r"(r[1]) : "r"(a));
}
__device__ __forceinline__ void mma16816(float* c, const uint32_t* a, const uint32_t* b) {
    asm volatile("mma.sync.aligned.m16n8k16.row.col.f32.bf16.bf16.f32 "
                 "{%0,%1,%2,%3}, {%4,%5,%6,%7}, {%8,%9}, {%0,%1,%2,%3};"
                 : "+f"(c[0]), "+f"(c[1]), "+f"(c[2]), "+f"(c[3])
                 : "r"(a[0]), "r"(a[1]), "r"(a[2]), "r"(a[3]), "r"(b[0]), "r"(b[1]));
}

// ---------------------------------------------------------------------------
// Kernel: convert W0/W1 -> transposed hi/lo bf16 splits; also zero g_cnt.
// grid covers max(32768, NSEG) threads.
// ---------------------------------------------------------------------------
__global__ __launch_bounds__(256)
void bconv_zero_kernel(const float* __restrict__ W0, const float* __restrict__ W1) {
    int i = blockIdx.x * blockDim.x + threadIdx.x;
    if (i < NSEG) g_cnt[i] = 0;
    if (i < 256 * 128) {
        int n = i >> 7, k = i & 127;
        const float* __restrict__ W = (n < 128) ? W0 : W1;
        float v = __ldg(W + k * 128 + (n & 127));
        __nv_bfloat16 h = __float2bfloat16(v);
        float r = v - __bfloat162float(h);
        g_Bt_hi[i] = h;
        g_Bt_lo[i] = __float2bfloat16(r);
    }
}

// ---------------------------------------------------------------------------
// Kernel: histogram of dst per segment (both edge sets in one grid)
// ---------------------------------------------------------------------------
__global__ __launch_bounds__(256)
void hist_kernel(const int* __restrict__ idx0, const int* __restrict__ idx1) {
    int i = blockIdx.x * blockDim.x + threadIdx.x;
    if (i >= 2 * N_EDGES) return;
    int set = (i >= N_EDGES) ? 1 : 0;
    int e   = i - set * N_EDGES;
    const int* __restrict__ idx = set ? idx1 : idx0;
    int dst = __ldg(idx + e);                     // edge_index[0] = dst
    atomicAdd(&g_cnt[set * N_NODES + dst], 1);
}

// ---------------------------------------------------------------------------
// Two-level exclusive scan of g_cnt -> g_off (+ cursor re-init into g_cnt)
// ---------------------------------------------------------------------------
__global__ __launch_bounds__(256)
void scan_blocksum_kernel() {
    __shared__ int warpsums[8];
    int b = blockIdx.x, t = threadIdx.x;
    int base = b * SCAN_BLK_ITEMS + t * 4;
    int s = 0;
#pragma unroll
    for (int k = 0; k < 4; k++) {
        int j = base + k;
        if (j < NSEG) s += g_cnt[j];
    }
    for (int o = 16; o > 0; o >>= 1) s += __shfl_down_sync(0xFFFFFFFFu, s, o);
    if ((t & 31) == 0) warpsums[t >> 5] = s;
    __syncthreads();
    if (t == 0) {
        int tot = 0;
#pragma unroll
        for (int w = 0; w < 8; w++) tot += warpsums[w];
        g_blocksums[b] = tot;
    }
}

__global__ __launch_bounds__(128)
void scan_top_kernel() {
    __shared__ int sh[128];
    int t = threadIdx.x;
    int v = (t < SCAN_NBLK) ? g_blocksums[t] : 0;
    sh[t] = v;
    __syncthreads();
    for (int d = 1; d < 128; d <<= 1) {
        int y = (t >= d) ? sh[t - d] : 0;
        __syncthreads();
        sh[t] += y;
        __syncthreads();
    }
    if (t < SCAN_NBLK) g_blockoff[t] = sh[t] - v;
    if (t == 127) g_off[NSEG] = sh[127];
}

__global__ __launch_bounds__(256)
void scan_final_kernel() {
    __shared__ int warpsums[8];
    int b = blockIdx.x, t = threadIdx.x;
    int lane = t & 31, w = t >> 5;
    int base = b * SCAN_BLK_ITEMS + t * 4;

    int c0 = 0, c1 = 0, c2 = 0, c3 = 0;
    if (base + 0 < NSEG) c0 = g_cnt[base + 0];
    if (base + 1 < NSEG) c1 = g_cnt[base + 1];
    if (base + 2 < NSEG) c2 = g_cnt[base + 2];
    if (base + 3 < NSEG) c3 = g_cnt[base + 3];
    int tsum = c0 + c1 + c2 + c3;

    int inc = tsum;
    for (int o = 1; o < 32; o <<= 1) {
        int y = __shfl_up_sync(0xFFFFFFFFu, inc, o);
        if (lane >= o) inc += y;
    }
    if (lane == 31) warpsums[w] = inc;
    __syncthreads();
    if (w == 0) {
        int ws = (lane < 8) ? warpsums[lane] : 0;
        for (int o = 1; o < 8; o <<= 1) {
            int y = __shfl_up_sync(0xFFFFFFFFu, ws, o);
            if (lane >= o) ws += y;
        }
        if (lane < 8) warpsums[lane] = ws;
    }
    __syncthreads();

    int texcl = g_blockoff[b] + (w ? warpsums[w - 1] : 0) + (inc - tsum);
    int o0 = texcl, o1 = o0 + c0, o2 = o1 + c1, o3 = o2 + c2;
    if (base + 0 < NSEG) { g_off[base + 0] = o0; g_cnt[base + 0] = o0; }
    if (base + 1 < NSEG) { g_off[base + 1] = o1; g_cnt[base + 1] = o1; }
    if (base + 2 < NSEG) { g_off[base + 2] = o2; g_cnt[base + 2] = o2; }
    if (base + 3 < NSEG) { g_off[base + 3] = o3; g_cnt[base + 3] = o3; }
}

// ---------------------------------------------------------------------------
// Kernel: scatter edges into CSR entry array (g_cnt = cursor)
// ---------------------------------------------------------------------------
__global__ __launch_bounds__(256)
void scatter_kernel(const float* __restrict__ vals0, const float* __restrict__ vals1,
                    const int* __restrict__ idx0,  const int* __restrict__ idx1) {
    int i = blockIdx.x * blockDim.x + threadIdx.x;
    if (i >= 2 * N_EDGES) return;
    int set = (i >= N_EDGES) ? 1 : 0;
    int e   = i - set * N_EDGES;
    const int*   __restrict__ idx = set ? idx1  : idx0;
    const float* __restrict__ vv  = set ? vals1 : vals0;

    int   dst = __ldg(idx + e);
    int   src = __ldg(idx + N_EDGES + e);
    float v   = __ldg(vv + e);

    int pos = atomicAdd(&g_cnt[set * N_NODES + dst], 1);
    g_entries[pos] = make_int2(src * 256 + set * 128, __float_as_int(v));
}

// ---------------------------------------------------------------------------
// Kernel: tensor-core GEMM  g_pre[m, nBase..nBase+128] = X @ [W0|W1] cols
// bf16x3 split emulating fp32: acc += Ahi*Bhi + Ahi*Blo + Alo*Bhi.
// Block 128M x 128N, 8 warps (2M x 4N), warp tile 64x32, K chunks of 32.
// ---------------------------------------------------------------------------
#define APAD 40   // smem row stride in elements (80 B -> conflict-free ldmatrix)

__global__ __launch_bounds__(256, 2)
void gemm_tc_kernel(const float* __restrict__ X) {
    __shared__ alignas(16) __nv_bfloat16 As[2][128 * APAD];  // [hi/lo][m][k]
    __shared__ alignas(16) __nv_bfloat16 Bs[2][128 * APAD];  // [hi/lo][n][k]

    const int mTile = blockIdx.x * 128;
    const int nBase = blockIdx.y * 128;          // 0 or 128 within 256-wide cols
    const int tid = threadIdx.x, lane = tid & 31, wid = tid >> 5;
    const int warp_m = wid >> 2, warp_n = wid & 3;

    float acc[4][4][4];
#pragma unroll
    for (int a = 0; a < 4; a++)
#pragma unroll
        for (int b = 0; b < 4; b++)
#pragma unroll
            for (int c = 0; c < 4; c++) acc[a][b][c] = 0.f;

    // ldmatrix source addresses (fixed per thread, k-offset varies)
    const int a_mrow = warp_m * 64 + (lane & 15);
    const int a_koff = ((lane >> 4) & 1) * 8;
    const int b_nrow = warp_n * 32 + (lane & 7);
    const int b_koff = ((lane >> 3) & 1) * 8;

    for (int kc = 0; kc < 4; kc++) {
        // ---- load A chunk 128x32 fp32 -> hi/lo bf16 in smem ----
#pragma unroll
        for (int i = 0; i < 4; i++) {
            int f = tid + i * 256;               // float4 index, 1024 total
            int row = f >> 3, col = (f & 7) * 4;
            int grow = mTile + row;
            float4 v = make_float4(0.f, 0.f, 0.f, 0.f);
            if (grow < N_NODES)
                v = *reinterpret_cast<const float4*>(X + (size_t)grow * 128 + kc * 32 + col);
            __nv_bfloat16 hx = __float2bfloat16(v.x);
            __nv_bfloat16 hy = __float2bfloat16(v.y);
            __nv_bfloat16 hz = __float2bfloat16(v.z);
            __nv_bfloat16 hw = __float2bfloat16(v.w);
            __nv_bfloat16 lx = __float2bfloat16(v.x - __bfloat162float(hx));
            __nv_bfloat16 ly = __float2bfloat16(v.y - __bfloat162float(hy));
            __nv_bfloat16 lz = __float2bfloat16(v.z - __bfloat162float(hz));
            __nv_bfloat16 lw = __float2bfloat16(v.w - __bfloat162float(hw));
            __nv_bfloat162* ph = reinterpret_cast<__nv_bfloat162*>(&As[0][row * APAD + col]);
            ph[0] = __nv_bfloat162(hx, hy);
            ph[1] = __nv_bfloat162(hz, hw);
            __nv_bfloat162* pl = reinterpret_cast<__nv_bfloat162*>(&As[1][row * APAD + col]);
            pl[0] = __nv_bfloat162(lx, ly);
            pl[1] = __nv_bfloat162(lz, lw);
        }
        // ---- load B chunk 128n x 32k (hi + lo) ----
#pragma unroll
        for (int i = 0; i < 4; i++) {
            int u = tid + i * 256;               // uint4 index, 1024 total
            int mat = u >> 9, q = u & 511;
            int n = q >> 2, kq = (q & 3) * 8;
            const __nv_bfloat16* src = (mat ? g_Bt_lo : g_Bt_hi)
                                       + (size_t)(nBase + n) * 128 + kc * 32 + kq;
            uint4 val = *reinterpret_cast<const uint4*>(src);
            *reinterpret_cast<uint4*>(&Bs[mat][n * APAD + kq]) = val;
        }
        __syncthreads();

#pragma unroll
        for (int ks = 0; ks < 2; ks++) {
            // B fragments for all 4 n-tiles (hi and lo)
            uint32_t bh[4][2], bl[4][2];
#pragma unroll
            for (int nt = 0; nt < 4; nt++) {
                int off = (b_nrow + nt * 8) * APAD + ks * 16 + b_koff;
                ldm_x2(bh[nt], smem_u32(&Bs[0][off]));
                ldm_x2(bl[nt], smem_u32(&Bs[1][off]));
            }
#pragma unroll
            for (int mt = 0; mt < 4; mt++) {
                int off = (a_mrow + mt * 16) * APAD + ks * 16 + a_koff;
                uint32_t ah[4], al[4];
                ldm_x4(ah, smem_u32(&As[0][off]));
                ldm_x4(al, smem_u32(&As[1][off]));
#pragma unroll
                for (int nt = 0; nt < 4; nt++) {
                    mma16816(acc[mt][nt], ah, bh[nt]);
                    mma16816(acc[mt][nt], ah, bl[nt]);
                    mma16816(acc[mt][nt], al, bh[nt]);
                }
            }
        }
        __syncthreads();
    }

    // ---- epilogue: write fp32 results to g_pre ----
#pragma unroll
    for (int mt = 0; mt < 4; mt++) {
        int r0 = mTile + warp_m * 64 + mt * 16 + (lane >> 2);
#pragma unroll
        for (int nt = 0; nt < 4; nt++) {
            int c = nBase + warp_n * 32 + nt * 8 + (lane & 3) * 2;
            if (r0 < N_NODES)
                *reinterpret_cast<float2*>(&g_pre[(size_t)r0 * 256 + c]) =
                    make_float2(acc[mt][nt][0], acc[mt][nt][1]);
            if (r0 + 8 < N_NODES)
                *reinterpret_cast<float2*>(&g_pre[(size_t)(r0 + 8) * 256 + c]) =
                    make_float2(acc[mt][nt][2], acc[mt][nt][3]);
        }
    }
}

// ---------------------------------------------------------------------------
// Kernel: CSR SpMM — one warp per dst row, register accumulation,
// fused bias + ReLU, single store. Entries read warp-uniform (L1 broadcast),
// inner loop unrolled x2 for gather MLP.
// ---------------------------------------------------------------------------
__global__ __launch_bounds__(256)
void spmm_csr_kernel(const float* __restrict__ bias, float* __restrict__ out) {
    const int warp = (blockIdx.x * blockDim.x + threadIdx.x) >> 5;
    const int lane = threadIdx.x & 31;
    if (warp >= N_NODES) return;
    const int r = warp;
    const int lo = lane * 4;

    float4 acc = make_float4(0.f, 0.f, 0.f, 0.f);

#pragma unroll
    for (int set = 0; set < 2; set++) {
        int seg = set * N_NODES + r;
        int e   = __ldg(&g_off[seg]);
        int end = __ldg(&g_off[seg + 1]);

        for (; e + 1 < end; e += 2) {
            int2 e0 = __ldg(&g_entries[e]);
            int2 e1 = __ldg(&g_entries[e + 1]);
            float4 p0 = *reinterpret_cast<const float4*>(g_pre + e0.x + lo);
            float4 p1 = *reinterpret_cast<const float4*>(g_pre + e1.x + lo);
            float v0 = __int_as_float(e0.y);
            float v1 = __int_as_float(e1.y);
            acc.x = fmaf(v0, p0.x, acc.x);
            acc.y = fmaf(v0, p0.y, acc.y);
            acc.z = fmaf(v0, p0.z, acc.z);
            acc.w = fmaf(v0, p0.w, acc.w);
            acc.x = fmaf(v1, p1.x, acc.x);
            acc.y = fmaf(v1, p1.y, acc.y);
            acc.z = fmaf(v1, p1.z, acc.z);
            acc.w = fmaf(v1, p1.w, acc.w);
        }
        if (e < end) {
            int2 e0 = __ldg(&g_entries[e]);
            float4 p0 = *reinterpret_cast<const float4*>(g_pre + e0.x + lo);
            float v0 = __int_as_float(e0.y);
            acc.x = fmaf(v0, p0.x, acc.x);
            acc.y = fmaf(v0, p0.y, acc.y);
            acc.z = fmaf(v0, p0.z, acc.z);
            acc.w = fmaf(v0, p0.w, acc.w);
        }
    }

    float4 b = *reinterpret_cast<const float4*>(bias + lo);
    acc.x = fmaxf(acc.x + b.x, 0.f);
    acc.y = fmaxf(acc.y + b.y, 0.f);
    acc.z = fmaxf(acc.z + b.z, 0.f);
    acc.w = fmaxf(acc.w + b.w, 0.f);
    *reinterpret_cast<float4*>(out + (size_t)r * D_OUT + lo) = acc;
}

// ---------------------------------------------------------------------------
// Launch. Inputs: x, W0, W1, bias, edge_vals0, edge_vals1, edge_index0, edge_index1
// ---------------------------------------------------------------------------
extern "C" void kernel_launch(void* const* d_in, const int* in_sizes, int n_in,
                              void* d_out, int out_size) {
    const float* x    = (const float*)d_in[0];
    const float* W0   = (const float*)d_in[1];
    const float* W1   = (const float*)d_in[2];
    const float* bias = (const float*)d_in[3];
    const float* ev0  = (const float*)d_in[4];
    const float* ev1  = (const float*)d_in[5];
    const int*   ei0  = (const int*)d_in[6];
    const int*   ei1  = (const int*)d_in[7];
    float*       out  = (float*)d_out;

    const int edgeThreads = 2 * N_EDGES;

    // W split/transpose + zero counters (fused)
    int bzThreads = (NSEG > 256 * 128) ? NSEG : 256 * 128;
    bconv_zero_kernel<<<(bzThreads + 255) / 256, 256>>>(W0, W1);

    // CSR build
    hist_kernel<<<(edgeThreads + 255) / 256, 256>>>(ei0, ei1);
    scan_blocksum_kernel<<<SCAN_NBLK, 256>>>();
    scan_top_kernel<<<1, 128>>>();
    scan_final_kernel<<<SCAN_NBLK, 256>>>();
    scatter_kernel<<<(edgeThreads + 255) / 256, 256>>>(ev0, ev1, ei0, ei1);

    // Tensor-core GEMM: g_pre = x @ [W0 | W1]  (bf16x3 split precision)
    dim3 gGrid((N_NODES + 127) / 128, 2);
    gemm_tc_kernel<<<gGrid, 256>>>(x);

    // CSR SpMM with fused bias + ReLU
    spmm_csr_kernel<<<(N_NODES * 32 + 255) / 256, 256>>>(bias, out);
}